// round 12
// baseline (speedup 1.0000x reference)
#include <cuda_runtime.h>

// ============================================================================
// FINAL / CONVERGED — LIF neuron group, T=1000 serial steps x 65536 neurons.
//
// Pure HBM stream: 512 MB read + 256 MB write, zero reuse, irreducible.
// ncu: 112.7us kernel x 6.61 TB/s == exactly 768 MB -> byte-floor-bound.
//
// Optimization history (all single-variable, theory-first):
//   R1  naive float4 streaming, 16K thr          587us  (DRAM 16%, latency-bound)
//   R2  A/B register pipeline (8 steps/blk)      154us  (DRAM 64%)
//   R4  1024 one-warp blocks (7-vs-6/SM) + 3buf  130us  (DRAM 75%)
//   R5  quad buffer + launch_bounds(32,7)        117us  (DRAM 83%)
//   R6  quint buffer                             117us  (depth saturated)
//   R7  scalar lanes / 2x warps                  FALSIFIED (DRAM -3pts)
//   R8  STAGES=5 x 8buf (finer bursts)           tie
//   R9  write-back stores                        FALSIFIED (-3.5pts)
//   R10 write-through stores                     FALSIFIED (-2.3pts)
//   R11 .cg loads (L1 bypass)                    exact tie
// Residual 17% DRAM-inactive = mixed 2:1 R/W bank-turnaround cost; not
// addressable from SM-side code. Converged at ~96% of practical ceiling.
// ============================================================================

#define NUM_NEURONS 65536
#define T_STEPS     1000
#define NVEC        (NUM_NEURONS / 2)     // 32768 float2 lanes
#define THREADS     32                    // 1 warp per block
#define BLOCKS      (NVEC / THREADS)      // 1024 blocks -> 7 vs 6 per SM
#define STAGES      8                     // timesteps per pipeline block (125 blocks)

__device__ __forceinline__ float2 lif_step(const float2 i2, const float2 n2,
                                           float2& V, float2& th)
{
    const float decay = 0.05f, eta = 0.1f, nstd = 0.1f;
    const float thmin = 0.5f, thmax = 2.0f;
    float2 s;
#define LIF_C(c)                                                     \
    {                                                                \
        float ie = fmaf(nstd, n2.c, i2.c);                           \
        float v  = fmaf(decay, ie - V.c, V.c);                       \
        bool  sp = (v >= th.c);                                      \
        s.c  = sp ? 1.0f : 0.0f;                                     \
        V.c  = sp ? 0.0f : v;                                        \
        th.c = fminf(fmaxf(fmaf(eta, s.c, th.c), thmin), thmax);     \
    }
    LIF_C(x) LIF_C(y)
#undef LIF_C
    return s;
}

__global__ __launch_bounds__(THREADS, 7)
void lif_kernel(const float2* __restrict__ icur,
                const float2* __restrict__ nz,
                float2* __restrict__ out)
{
    const int idx = blockIdx.x * THREADS + threadIdx.x;   // 0 .. NVEC-1

    const float2* ip = icur + idx;
    const float2* np = nz   + idx;
    float2*       op = out  + idx;

    float2 V  = make_float2(0.0f, 0.0f);
    float2 th = make_float2(1.0f, 1.0f);

    float2 AI[STAGES], AN[STAGES];
    float2 BI[STAGES], BN[STAGES];
    float2 CI[STAGES], CN[STAGES];
    float2 DI[STAGES], DN[STAGES];
    float2 EI[STAGES], EN[STAGES];

    // blk b covers timesteps [b*STAGES, (b+1)*STAGES)
#define LOAD_BLK(I_, N_, b)                                           \
    _Pragma("unroll")                                                 \
    for (int j = 0; j < STAGES; j++) {                                \
        I_[j] = __ldcg(ip + (size_t)((b) * STAGES + j) * NVEC);       \
        N_[j] = __ldcg(np + (size_t)((b) * STAGES + j) * NVEC);      \
    }

#define COMP_BLK(I_, N_, b)                                           \
    _Pragma("unroll")                                                 \
    for (int j = 0; j < STAGES; j++) {                                \
        float2 s = lif_step(I_[j], N_[j], V, th);                     \
        __stcs(op + (size_t)((b) * STAGES + j) * NVEC, s);            \
    }

    // 125 blocks of 8. Quint buffer: loads run 4 blocks ahead of compute.
    LOAD_BLK(AI, AN, 0)
    LOAD_BLK(BI, BN, 1)
    LOAD_BLK(CI, CN, 2)
    LOAD_BLK(DI, DN, 3)

    for (int p = 0; p < 24; p++) {
        const int b = 5 * p;                                 // 0,5,...,115
        LOAD_BLK(EI, EN, b + 4)   COMP_BLK(AI, AN, b)        // load <= 119
        LOAD_BLK(AI, AN, b + 5)   COMP_BLK(BI, BN, b + 1)    // load <= 120
        LOAD_BLK(BI, BN, b + 6)   COMP_BLK(CI, CN, b + 2)    // load <= 121
        LOAD_BLK(CI, CN, b + 7)   COMP_BLK(DI, DN, b + 3)    // load <= 122
        LOAD_BLK(DI, DN, b + 8)   COMP_BLK(EI, EN, b + 4)    // load <= 123
    }
    // computed 0..119; A=120, B=121, C=122, D=123
    LOAD_BLK(EI, EN, 124)   COMP_BLK(AI, AN, 120)
    COMP_BLK(BI, BN, 121)
    COMP_BLK(CI, CN, 122)
    COMP_BLK(DI, DN, 123)
    COMP_BLK(EI, EN, 124)

#undef LOAD_BLK
#undef COMP_BLK
}

extern "C" void kernel_launch(void* const* d_in, const int* in_sizes, int n_in,
                              void* d_out, int out_size)
{
    const float2* icur = (const float2*)d_in[0];   // input_current (T, N) f32
    const float2* nz   = (const float2*)d_in[1];   // noise         (T, N) f32
    float2*       out  = (float2*)d_out;           // spikes        (T, N) f32

    lif_kernel<<<BLOCKS, THREADS>>>(icur, nz, out);
}